// round 1
// baseline (speedup 1.0000x reference)
#include <cuda_runtime.h>

// Problem constants (fixed by the reference setup_inputs):
//   E = 2048, N = 1024, SIG = 64, DT = 1e-6
// Output: [N+2E, 2E+N] = [5120, 5120] float32, row-major.
//
// Layout:
//   rows [0, N):        [ M (N x E) | 0 (N x E) | 0 (N x N) ]
//   rows [N, N+E):      [ 0 (E x E) | I_E       | -M^T (E x N) ]
//   rows [N+E, N+2E):   [ diag(z)   | diag(y)   | 0 (E x N) ]

#define NN   1024
#define EE   2048
#define SIGW 64
#define CC   (2 * EE + NN)   // 5120 columns
#define RR   (NN + 2 * EE)   // 5120 rows
#define C4   (CC / 4)        // 1280 float4 per row
#define DTC  1e-6f

__global__ void __launch_bounds__(256)
coeff_build_kernel(const float* __restrict__ M,
                   const float* __restrict__ params,
                   const float* __restrict__ sw_params,
                   const int*   __restrict__ kinds,
                   const int*   __restrict__ time_ptr,
                   float4*      __restrict__ out)
{
    const int idx = blockIdx.x * blockDim.x + threadIdx.x;
    const int row = idx / C4;
    const int c4  = idx - row * C4;
    const int c   = c4 * 4;

    float4 v = make_float4(0.f, 0.f, 0.f, 0.f);

    if (row < NN) {
        // Top block: M in cols [0, E), zeros elsewhere. Coalesced float4 copy.
        if (c < EE) {
            v = *reinterpret_cast<const float4*>(M + row * EE + c);
        }
    } else if (row < NN + EE) {
        const int e = row - NN;
        if (c >= 2 * EE) {
            // -M^T block: out[N+e, 2E+n] = -M[n, e]. Column gather from M.
            const int n = c - 2 * EE;
            const float* col = M + e;
            v.x = -col[(size_t)(n + 0) * EE];
            v.y = -col[(size_t)(n + 1) * EE];
            v.z = -col[(size_t)(n + 2) * EE];
            v.w = -col[(size_t)(n + 3) * EE];
        } else if (c >= EE) {
            // Identity block: 1.0 at col (E + e).
            const int d = e - (c - EE);
            if ((unsigned)d < 4u) ((float*)&v)[d] = 1.0f;
        }
        // cols [0, E): zeros
    } else {
        // Element block: diag(z) at col e, diag(y) at col (E + e).
        const int e  = row - NN - EE;
        const int dz = e - c;
        const int dy = (EE + e) - c;
        if ((unsigned)dz < 4u || (unsigned)dy < 4u) {
            const int   t     = *time_ptr;
            const float p     = params[e];
            const int   k     = kinds[e];
            // sigmoid(x) > 0.5  <=>  x > 0
            const bool  sw_on = sw_params[(size_t)e * SIGW + t] > 0.0f;
            const float ndt   = -DTC / p;

            float z, y;
            switch (k) {
                case 0:  z = -p;                  y = 1.0f;                 break; // R
                case 1:  z = 0.0f;                y = 1.0f;                 break; // IVS
                case 2:  z = 1.0f;                y = 0.0f;                 break; // VC
                case 3:  z = sw_on ? 0.0f : 1.0f; y = sw_on ? 1.0f : 0.0f;  break; // SW
                case 4:  z = ndt;                 y = 1.0f;                 break; // C
                default: z = 1.0f;                y = ndt;                  break; // L
            }
            if ((unsigned)dz < 4u) ((float*)&v)[dz] = z;
            if ((unsigned)dy < 4u) ((float*)&v)[dy] = y;
        }
    }

    out[idx] = v;
}

extern "C" void kernel_launch(void* const* d_in, const int* in_sizes, int n_in,
                              void* d_out, int out_size)
{
    const float* M         = (const float*)d_in[0];  // [N, E]
    const float* params    = (const float*)d_in[1];  // [E]
    const float* sw_params = (const float*)d_in[2];  // [E, SIG]
    const int*   kinds     = (const int*)d_in[3];    // [E]
    const int*   time_ptr  = (const int*)d_in[4];    // scalar

    float4* out = (float4*)d_out;

    const int total4  = RR * C4;           // 6,553,600 float4 stores
    const int threads = 256;
    const int blocks  = total4 / threads;  // 25,600 (exact)

    coeff_build_kernel<<<blocks, threads>>>(M, params, sw_params, kinds, time_ptr, out);
}

// round 3
// speedup vs baseline: 1.2594x; 1.2594x over previous
#include <cuda_runtime.h>

// Output: [N+2E, 2E+N] = [5120, 5120] float32, row-major.
//   rows [0, N):        [ M (N x E) | 0 | 0 ]
//   rows [N, N+E):      [ 0 | I_E | -M^T (E x N) ]
//   rows [N+E, N+2E):   [ diag(z) | diag(y) | 0 ]
//
// Block-role dispatch (one launch, uniform work per block):
//   [0, 5120):             top rows, float4 copy/zero
//   [5120, 13312):         middle rows cols [0,2E): zeros + identity, float4
//   [13312, 15360):        -M^T via 32x32 smem tile transpose (float4 stores)
//   [15360, 25600):        bottom rows: zeros + z/y diagonals, float4

#define NN   1024
#define EE   2048
#define SIGW 64
#define CC   (2 * EE + NN)   // 5120
#define C4   (CC / 4)        // 1280
#define DTC  1e-6f

#define TOP_B   5120         // N * C4 / 256                 = 5120
#define MID_B   8192         // E * (2E/4) / 256 = 2048*1024/256
#define TR_B    2048         // (E/32) * (N/32) = 64*32
#define BOT_B   10240        // E * C4 / 256

__global__ void __launch_bounds__(256)
coeff_build_kernel(const float* __restrict__ M,
                   const float* __restrict__ params,
                   const float* __restrict__ sw_params,
                   const int*   __restrict__ kinds,
                   const int*   __restrict__ time_ptr,
                   float*       __restrict__ out)
{
    __shared__ float tile[32][33];

    const int b   = blockIdx.x;
    const int tid = threadIdx.x;

    if (b < TOP_B) {
        // ---- Top block: rows [0, N). M copy in cols [0,E), zeros after.
        const int idx = b * 256 + tid;          // float4 index
        const int row = idx / C4;
        const int c4  = idx - row * C4;
        const int c   = c4 * 4;
        float4 v = make_float4(0.f, 0.f, 0.f, 0.f);
        if (c < EE)
            v = *reinterpret_cast<const float4*>(M + row * EE + c);
        reinterpret_cast<float4*>(out)[(size_t)row * C4 + c4] = v;
        return;
    }

    if (b < TOP_B + MID_B) {
        // ---- Middle rows, cols [0, 2E): zeros + identity at col (E + e).
        // 1024 float4 per row (cols 0..4095).
        const int idx = (b - TOP_B) * 256 + tid;
        const int e   = idx >> 10;              // / 1024 float4 per row-span
        const int c4  = idx & 1023;
        const int c   = c4 * 4;
        float4 v = make_float4(0.f, 0.f, 0.f, 0.f);
        const int d = e - (c - EE);             // identity hit: c>=E and e-(c-E) in [0,4)
        if (c >= EE && (unsigned)d < 4u)
            ((float*)&v)[d] = 1.0f;
        reinterpret_cast<float4*>(out)[(size_t)(NN + e) * C4 + c4] = v;
        return;
    }

    if (b < TOP_B + MID_B + TR_B) {
        // ---- -M^T block via smem transpose.
        // out[N+e][2E+n] = -M[n][e]; tile[n_local][e_local].
        const int t  = b - (TOP_B + MID_B);
        const int tn = t & 31;                  // 32 tiles along n
        const int te = t >> 5;                  // 64 tiles along e
        const int n0 = tn * 32;
        const int e0 = te * 32;
        const int tx = tid & 31;
        const int ty = tid >> 5;                // 0..7

        #pragma unroll
        for (int i = 0; i < 4; i++) {
            const int r = ty + i * 8;           // local n
            tile[r][tx] = M[(size_t)(n0 + r) * EE + (e0 + tx)];
        }
        __syncthreads();

        // Write: 32 rows x 8 float4. r = local e, q = float4 slot along n.
        const int r = tid >> 3;                 // 0..31
        const int q = tid & 7;                  // 0..7
        float4 v;
        v.x = -tile[q * 4 + 0][r];
        v.y = -tile[q * 4 + 1][r];
        v.z = -tile[q * 4 + 2][r];
        v.w = -tile[q * 4 + 3][r];
        *reinterpret_cast<float4*>(
            out + (size_t)(NN + e0 + r) * CC + (2 * EE + n0 + q * 4)) = v;
        return;
    }

    // ---- Bottom block: rows [N+E, N+2E). diag(z) at col e, diag(y) at E+e.
    {
        const int idx = (b - (TOP_B + MID_B + TR_B)) * 256 + tid;
        const int e   = idx / C4;
        const int c4  = idx - e * C4;
        const int c   = c4 * 4;
        float4 v = make_float4(0.f, 0.f, 0.f, 0.f);
        const int dz = e - c;
        const int dy = (EE + e) - c;
        if ((unsigned)dz < 4u || (unsigned)dy < 4u) {
            const int   tm    = *time_ptr;
            const float p     = params[e];
            const int   k     = kinds[e];
            const bool  sw_on = sw_params[(size_t)e * SIGW + tm] > 0.0f;  // sigmoid(x)>0.5 <=> x>0
            const float ndt   = -DTC / p;
            float z, y;
            switch (k) {
                case 0:  z = -p;                  y = 1.0f;                 break; // R
                case 1:  z = 0.0f;                y = 1.0f;                 break; // IVS
                case 2:  z = 1.0f;                y = 0.0f;                 break; // VC
                case 3:  z = sw_on ? 0.0f : 1.0f; y = sw_on ? 1.0f : 0.0f;  break; // SW
                case 4:  z = ndt;                 y = 1.0f;                 break; // C
                default: z = 1.0f;                y = ndt;                  break; // L
            }
            if ((unsigned)dz < 4u) ((float*)&v)[dz] = z;
            if ((unsigned)dy < 4u) ((float*)&v)[dy] = y;
        }
        reinterpret_cast<float4*>(out)[(size_t)(NN + EE + e) * C4 + c4] = v;
    }
}

extern "C" void kernel_launch(void* const* d_in, const int* in_sizes, int n_in,
                              void* d_out, int out_size)
{
    const float* M         = (const float*)d_in[0];
    const float* params    = (const float*)d_in[1];
    const float* sw_params = (const float*)d_in[2];
    const int*   kinds     = (const int*)d_in[3];
    const int*   time_ptr  = (const int*)d_in[4];

    const int blocks = TOP_B + MID_B + TR_B + BOT_B;   // 25600
    coeff_build_kernel<<<blocks, 256>>>(M, params, sw_params, kinds, time_ptr,
                                        (float*)d_out);
}

// round 4
// speedup vs baseline: 1.2748x; 1.0122x over previous
#include <cuda_runtime.h>

// Output: [N+2E, 2E+N] = [5120, 5120] float32, row-major.
//   rows [0, N):        [ M (N x E) | 0 | 0 ]
//   rows [N, N+E):      [ 0 | I_E | -M^T (E x N) ]
//   rows [N+E, N+2E):   [ diag(z) | diag(y) | 0 ]
//
// Block roles (uniform per block, no per-thread division):
//   [0, 1024):       TOP: one output row each; 5 float4/thread
//   [1024, 3072):    MID: one row, cols [0,4096); 4 float4/thread (zeros + I)
//   [3072, 5120):    -M^T 32x32 smem tile transpose (covers mid cols [4096,5120))
//   [5120, 7168):    BOT: one row each; 5 float4/thread (zeros + z/y diag)

#define NN   1024
#define EE   2048
#define SIGW 64
#define CC   (2 * EE + NN)   // 5120
#define C4   (CC / 4)        // 1280
#define DTC  1e-6f

#define TOP_B 1024
#define MID_B 2048
#define TR_B  2048
#define BOT_B 2048

__global__ void __launch_bounds__(256)
coeff_build_kernel(const float* __restrict__ M,
                   const float* __restrict__ params,
                   const float* __restrict__ sw_params,
                   const int*   __restrict__ kinds,
                   const int*   __restrict__ time_ptr,
                   float*       __restrict__ out)
{
    __shared__ float tile[32][33];

    const int b   = blockIdx.x;
    const int tid = threadIdx.x;
    const float4 zero4 = make_float4(0.f, 0.f, 0.f, 0.f);

    if (b < TOP_B) {
        // ---- TOP: row = b. cols [0,E) = M row (512 f4), rest zeros.
        const int row = b;
        const float4* Mrow = reinterpret_cast<const float4*>(M + (size_t)row * EE);
        float4* orow = reinterpret_cast<float4*>(out) + (size_t)row * C4;
        #pragma unroll
        for (int k = 0; k < 5; k++) {
            const int c4 = tid + k * 256;
            orow[c4] = (c4 < 512) ? Mrow[c4] : zero4;
        }
        return;
    }

    if (b < TOP_B + MID_B) {
        // ---- MID: row = N + e, cols [0, 4096): zeros + 1.0 at col (E + e).
        const int e = b - TOP_B;
        float4* orow = reinterpret_cast<float4*>(out) + (size_t)(NN + e) * C4;
        const int idf4  = 512 + (e >> 2);   // float4 index of identity element
        const int idcmp = e & 3;
        #pragma unroll
        for (int k = 0; k < 4; k++) {
            const int c4 = tid + k * 256;
            float4 v = zero4;
            if (c4 == idf4) ((float*)&v)[idcmp] = 1.0f;
            orow[c4] = v;
        }
        return;
    }

    if (b < TOP_B + MID_B + TR_B) {
        // ---- -M^T via smem transpose: out[N+e][2E+n] = -M[n][e].
        const int t  = b - (TOP_B + MID_B);
        const int tn = t & 31;              // 32 tiles along n
        const int te = t >> 5;              // 64 tiles along e
        const int n0 = tn * 32;
        const int e0 = te * 32;
        const int tx = tid & 31;
        const int ty = tid >> 5;            // 0..7

        #pragma unroll
        for (int i = 0; i < 4; i++) {
            const int r = ty + i * 8;       // local n
            tile[r][tx] = M[(size_t)(n0 + r) * EE + (e0 + tx)];
        }
        __syncthreads();

        const int r = tid >> 3;             // local e, 0..31
        const int q = tid & 7;              // float4 slot along n, 0..7
        float4 v;
        v.x = -tile[q * 4 + 0][r];
        v.y = -tile[q * 4 + 1][r];
        v.z = -tile[q * 4 + 2][r];
        v.w = -tile[q * 4 + 3][r];
        *reinterpret_cast<float4*>(
            out + (size_t)(NN + e0 + r) * CC + (2 * EE + n0 + q * 4)) = v;
        return;
    }

    // ---- BOT: row = N + E + e. diag(z) at col e, diag(y) at col E+e, rest 0.
    {
        const int e = b - (TOP_B + MID_B + TR_B);
        float4* orow = reinterpret_cast<float4*>(out) + (size_t)(NN + EE + e) * C4;

        const int   tm    = *time_ptr;
        const float p     = params[e];
        const int   kk    = kinds[e];
        const bool  sw_on = sw_params[(size_t)e * SIGW + tm] > 0.0f; // sigmoid(x)>0.5 <=> x>0
        const float ndt   = -DTC / p;
        float z, y;
        switch (kk) {
            case 0:  z = -p;                  y = 1.0f;                 break; // R
            case 1:  z = 0.0f;                y = 1.0f;                 break; // IVS
            case 2:  z = 1.0f;                y = 0.0f;                 break; // VC
            case 3:  z = sw_on ? 0.0f : 1.0f; y = sw_on ? 1.0f : 0.0f;  break; // SW
            case 4:  z = ndt;                 y = 1.0f;                 break; // C
            default: z = 1.0f;                y = ndt;                  break; // L
        }

        const int zf4  = e >> 2;            // float4 index of z element
        const int yf4  = 512 + (e >> 2);    // float4 index of y element
        const int comp = e & 3;

        #pragma unroll
        for (int k = 0; k < 5; k++) {
            const int c4 = tid + k * 256;
            float4 v = zero4;
            if (c4 == zf4) ((float*)&v)[comp] = z;
            if (c4 == yf4) ((float*)&v)[comp] = y;
            orow[c4] = v;
        }
    }
}

extern "C" void kernel_launch(void* const* d_in, const int* in_sizes, int n_in,
                              void* d_out, int out_size)
{
    const float* M         = (const float*)d_in[0];
    const float* params    = (const float*)d_in[1];
    const float* sw_params = (const float*)d_in[2];
    const int*   kinds     = (const int*)d_in[3];
    const int*   time_ptr  = (const int*)d_in[4];

    const int blocks = TOP_B + MID_B + TR_B + BOT_B;   // 7168
    coeff_build_kernel<<<blocks, 256>>>(M, params, sw_params, kinds, time_ptr,
                                        (float*)d_out);
}